// round 9
// baseline (speedup 1.0000x reference)
#include <cuda_runtime.h>

#define BN 8
#define JN 64
#define CN 32
#define CG 16              // channels per interp-block group (grid.z = CN/CG = 2)
#define HT 8
#define HIMG_ 256
#define WIMG_ 256
#define HW (HIMG_*WIMG_)

__device__ __forceinline__ int box_width(const float* bx)
{
    float bw = bx[2] - bx[0];
    float bh = bx[3] - bx[1];
    // widths = int32( (bw/bh) * 8 ) in float32 arithmetic — keep EXACT
    return (int)(__fmul_rn(__fdiv_rn(bw, bh), 8.0f));
}

// ---------------------------------------------------------------------------
// Kernel 1: pure streaming zero-fill of the masked region + mask output.
// One block per box (bj); thread r owns output row r = c*8+i of that box.
// ---------------------------------------------------------------------------
__global__ void __launch_bounds__(256)
zerofill_kernel(const float* __restrict__ boxes,
                float* __restrict__ out,
                int max_w, int mask_mode)
{
    const int bj = blockIdx.x;                 // 0 .. B*J-1
    const int rrow = threadIdx.x;              // 0 .. 255 == (c*HT + i)

    const int width = box_width(boxes + bj * 5);
    const int chw = HT * max_w;

    // ---- mask ----
    if (mask_mode == 0) {
        float* maskp = out + BN * JN * CN * chw + bj * max_w;
        for (int k = threadIdx.x; k < max_w; k += blockDim.x)
            maskp[k] = (k < width) ? 1.0f : 0.0f;
    } else if (mask_mode == 1) {
        unsigned char* maskp =
            (unsigned char*)(out + BN * JN * CN * chw) + bj * max_w;
        for (int k = threadIdx.x; k < max_w; k += blockDim.x)
            maskp[k] = (k < width) ? (unsigned char)1 : (unsigned char)0;
    }

    // ---- zero row segment [width, max_w) ----
    float* rowp = out + bj * CN * chw + rrow * max_w;   // row base, 16B-aligned iff max_w%4==0
    int k = min(width, max_w);

    // scalar head until 16B alignment of (rowp + k)
    int head = (4 - (k & 3)) & 3;
    #pragma unroll
    for (int h = 0; h < 3; h++) {
        if (h < head && k < max_w) { rowp[k] = 0.0f; k++; }
    }
    const float4 z = make_float4(0.f, 0.f, 0.f, 0.f);
    for (; k + 3 < max_w; k += 4)
        *(float4*)(rowp + k) = z;
    for (; k < max_w; k++)
        rowp[k] = 0.0f;
}

// ---------------------------------------------------------------------------
// Kernel 2: bilinear interpolation for the live region only (k < width).
// ---------------------------------------------------------------------------
__global__ void roirotate_kernel(const float* __restrict__ image,
                                 const float* __restrict__ boxes,
                                 float* __restrict__ out,
                                 int max_w, float inv_w)
{
    const int bj = blockIdx.y;               // 0 .. B*J-1
    const int b  = bj >> 6;                  // JN = 64
    const int c0 = blockIdx.z * CG;

    const float* bx = boxes + bj * 5;
    float l = bx[0];
    float t = bx[1];

    const int width = box_width(bx);
    float bw = bx[2] - l;
    float bh = bx[3] - t;
    float each_w = bw / (float)(width - 1);
    float each_h = bh * (1.0f / 7.0f);        // HEIGHT-1 = 7

    const int chw = HT * max_w;               // per-channel output stride
    const float* imgb = image + (b * CN + c0) * HW;
    float* outb = out + (bj * CN + c0) * chw;

    const int idx = blockIdx.x * blockDim.x + threadIdx.x;   // over HT*max_w
    if (idx >= chw) return;

    // i = idx / max_w, k = idx % max_w  via float reciprocal + exact fixup
    int i = (int)((float)idx * inv_w);
    int k = idx - i * max_w;
    if (k < 0)           { i--; k += max_w; }
    else if (k >= max_w) { i++; k -= max_w; }

    if (k >= width) return;                   // zerofill kernel owns this region

    float x = (float)k * each_w + l;
    float y = (float)i * each_h + t;

    float fx = floorf(x), fy = floorf(y);
    int x0 = min(max((int)fx,     0), WIMG_ - 1);
    int x1 = min(max((int)fx + 1, 0), WIMG_ - 1);
    int y0 = min(max((int)fy,     0), HIMG_ - 1);
    int y1 = min(max((int)fy + 1, 0), HIMG_ - 1);

    float wx0 = x - (float)x0;     // weight for x1 side
    float wx1 = (float)x1 - x;     // weight for x0 side
    float wy0 = y - (float)y0;
    float wy1 = (float)y1 - y;

    float wa = wx1 * wy1;   // (y0,x0)
    float wb = wx1 * wy0;   // (y1,x0)
    float wc = wx0 * wy1;   // (y0,x1)
    float wd = wx0 * wy0;   // (y1,x1)

    const int o00 = y0 * WIMG_ + x0;
    const int o01 = y0 * WIMG_ + x1;
    const int o10 = y1 * WIMG_ + x0;
    const int o11 = y1 * WIMG_ + x1;

    const float* ip = imgb;
    float* o = outb + idx;
    #pragma unroll 4
    for (int c = 0; c < CG; c++) {
        float v = __ldg(ip + o00) * wa
                + __ldg(ip + o10) * wb
                + __ldg(ip + o01) * wc
                + __ldg(ip + o11) * wd;
        __stcg(o, v);
        ip += HW;
        o  += chw;
    }
}

extern "C" void kernel_launch(void* const* d_in, const int* in_sizes, int n_in,
                              void* d_out, int out_size)
{
    const float* image = (const float*)d_in[0];
    const float* boxes = (const float*)d_in[1];
    float* out = (float*)d_out;

    // Derive max_w from out_size (host-side, no sync needed).
    // res elems per unit max_w: B*J*C*H = 131072 ; mask elems per unit: B*J = 512
    const long long per_res = (long long)BN * JN * CN * HT;     // 131072
    const long long per_fmask = per_res + (long long)BN * JN;   // 131584 (float mask)
    const long long per_u8 = per_res + (long long)BN * JN / 4;  // 131200 (u8 mask packed into f32 elems)

    int max_w, mask_mode;
    long long osz = (long long)out_size;
    if (osz % per_fmask == 0) {
        max_w = (int)(osz / per_fmask);
        mask_mode = 0;
    } else if (osz % per_u8 == 0) {
        max_w = (int)(osz / per_u8);
        mask_mode = 1;
    } else if (osz % per_res == 0) {
        max_w = (int)(osz / per_res);
        mask_mode = 2;
    } else {
        // fallback: assume float-mask layout, round down
        max_w = (int)(osz / per_fmask);
        mask_mode = 0;
    }

    // 1) zero-fill masked region + mask (pure streaming writes)
    zerofill_kernel<<<BN * JN, 256>>>(boxes, out, max_w, mask_mode);

    // 2) interpolation for the live region
    const int block = 256;
    int slices = (HT * max_w + block - 1) / block;
    dim3 grid(slices, BN * JN, CN / CG);
    float inv_w = 1.0f / (float)max_w;
    roirotate_kernel<<<grid, block>>>(image, boxes, out, max_w, inv_w);
}

// round 10
// speedup vs baseline: 1.3457x; 1.3457x over previous
#include <cuda_runtime.h>
#include <stdint.h>

#define BN 8
#define JN 64
#define CN 32
#define CG 16              // channels per interp-block group (grid.z = CN/CG = 2)
#define HT 8
#define HIMG_ 256
#define WIMG_ 256
#define HW (HIMG_*WIMG_)

__device__ __forceinline__ int box_width(const float* bx)
{
    float bw = bx[2] - bx[0];
    float bh = bx[3] - bx[1];
    // widths = int32( (bw/bh) * 8 ) in float32 arithmetic — keep EXACT
    return (int)(__fmul_rn(__fdiv_rn(bw, bh), 8.0f));
}

// ---------------------------------------------------------------------------
// Kernel 1: streaming zero-fill of the masked region + mask output.
// One block per box. Warp w owns rows r = w, w+8, ..., w+248 (256 rows =
// CN*HT). Lanes stride float4 across the row segment -> fully coalesced.
// ---------------------------------------------------------------------------
__global__ void __launch_bounds__(256)
zerofill_kernel(const float* __restrict__ boxes,
                float* __restrict__ out,
                int max_w, int mask_mode)
{
    const int bj   = blockIdx.x;              // 0 .. B*J-1
    const int warp = threadIdx.x >> 5;
    const int lane = threadIdx.x & 31;

    const int width = box_width(boxes + bj * 5);
    const int chw = HT * max_w;

    // ---- mask ----
    if (mask_mode == 0) {
        float* maskp = out + BN * JN * CN * chw + bj * max_w;
        for (int k = threadIdx.x; k < max_w; k += blockDim.x)
            maskp[k] = (k < width) ? 1.0f : 0.0f;
    } else if (mask_mode == 1) {
        unsigned char* maskp =
            (unsigned char*)(out + BN * JN * CN * chw) + bj * max_w;
        for (int k = threadIdx.x; k < max_w; k += blockDim.x)
            maskp[k] = (k < width) ? (unsigned char)1 : (unsigned char)0;
    }

    const int kz = min(width, max_w);         // zero region start
    float* boxbase = out + bj * CN * chw;

    const float4 z4 = make_float4(0.f, 0.f, 0.f, 0.f);

    for (int r = warp; r < CN * HT; r += 8) {
        float* rowp = boxbase + r * max_w;

        // scalar head until (rowp + k) is 16B-aligned
        uintptr_t a4 = ((uintptr_t)(rowp + kz)) >> 2;
        int head = (int)((4 - (a4 & 3)) & 3);
        int k = kz;
        if (lane < head && k + lane < max_w)
            rowp[k + lane] = 0.0f;
        k += head;
        if (k > max_w) k = max_w;

        // float4 body, lanes stride 32 quads
        for (int kq = k + lane * 4; kq + 3 < max_w; kq += 128)
            *(float4*)(rowp + kq) = z4;

        // scalar tail (max_w not multiple of 4)
        int tail_start = k + ((max_w - k) & ~3);
        if (lane < (max_w - tail_start))
            rowp[tail_start + lane] = 0.0f;
    }
}

// ---------------------------------------------------------------------------
// Kernel 2: bilinear interpolation for the live region only (k < width).
// ---------------------------------------------------------------------------
__global__ void roirotate_kernel(const float* __restrict__ image,
                                 const float* __restrict__ boxes,
                                 float* __restrict__ out,
                                 int max_w, float inv_w)
{
    const int bj = blockIdx.y;               // 0 .. B*J-1
    const int b  = bj >> 6;                  // JN = 64
    const int c0 = blockIdx.z * CG;

    const float* bx = boxes + bj * 5;
    float l = bx[0];
    float t = bx[1];

    const int width = box_width(bx);
    float bw = bx[2] - l;
    float bh = bx[3] - t;
    float each_w = bw / (float)(width - 1);
    float each_h = bh * (1.0f / 7.0f);        // HEIGHT-1 = 7

    const int chw = HT * max_w;               // per-channel output stride
    const float* imgb = image + (b * CN + c0) * HW;
    float* outb = out + (bj * CN + c0) * chw;

    const int idx = blockIdx.x * blockDim.x + threadIdx.x;   // over HT*max_w
    if (idx >= chw) return;

    // i = idx / max_w, k = idx % max_w  via float reciprocal + exact fixup
    int i = (int)((float)idx * inv_w);
    int k = idx - i * max_w;
    if (k < 0)           { i--; k += max_w; }
    else if (k >= max_w) { i++; k -= max_w; }

    if (k >= width) return;                   // zerofill kernel owns this region

    float x = (float)k * each_w + l;
    float y = (float)i * each_h + t;

    float fx = floorf(x), fy = floorf(y);
    int x0 = min(max((int)fx,     0), WIMG_ - 1);
    int x1 = min(max((int)fx + 1, 0), WIMG_ - 1);
    int y0 = min(max((int)fy,     0), HIMG_ - 1);
    int y1 = min(max((int)fy + 1, 0), HIMG_ - 1);

    float wx0 = x - (float)x0;     // weight for x1 side
    float wx1 = (float)x1 - x;     // weight for x0 side
    float wy0 = y - (float)y0;
    float wy1 = (float)y1 - y;

    float wa = wx1 * wy1;   // (y0,x0)
    float wb = wx1 * wy0;   // (y1,x0)
    float wc = wx0 * wy1;   // (y0,x1)
    float wd = wx0 * wy0;   // (y1,x1)

    const int o00 = y0 * WIMG_ + x0;
    const int o01 = y0 * WIMG_ + x1;
    const int o10 = y1 * WIMG_ + x0;
    const int o11 = y1 * WIMG_ + x1;

    const float* ip = imgb;
    float* o = outb + idx;
    #pragma unroll 8
    for (int c = 0; c < CG; c++) {
        float v = __ldg(ip + o00) * wa
                + __ldg(ip + o10) * wb
                + __ldg(ip + o01) * wc
                + __ldg(ip + o11) * wd;
        __stcg(o, v);
        ip += HW;
        o  += chw;
    }
}

extern "C" void kernel_launch(void* const* d_in, const int* in_sizes, int n_in,
                              void* d_out, int out_size)
{
    const float* image = (const float*)d_in[0];
    const float* boxes = (const float*)d_in[1];
    float* out = (float*)d_out;

    // Derive max_w from out_size (host-side, no sync needed).
    // res elems per unit max_w: B*J*C*H = 131072 ; mask elems per unit: B*J = 512
    const long long per_res = (long long)BN * JN * CN * HT;     // 131072
    const long long per_fmask = per_res + (long long)BN * JN;   // 131584 (float mask)
    const long long per_u8 = per_res + (long long)BN * JN / 4;  // 131200 (u8 mask packed into f32 elems)

    int max_w, mask_mode;
    long long osz = (long long)out_size;
    if (osz % per_fmask == 0) {
        max_w = (int)(osz / per_fmask);
        mask_mode = 0;
    } else if (osz % per_u8 == 0) {
        max_w = (int)(osz / per_u8);
        mask_mode = 1;
    } else if (osz % per_res == 0) {
        max_w = (int)(osz / per_res);
        mask_mode = 2;
    } else {
        // fallback: assume float-mask layout, round down
        max_w = (int)(osz / per_fmask);
        mask_mode = 0;
    }

    // 1) zero-fill masked region + mask (coalesced streaming writes)
    zerofill_kernel<<<BN * JN, 256>>>(boxes, out, max_w, mask_mode);

    // 2) interpolation for the live region
    const int block = 256;
    int slices = (HT * max_w + block - 1) / block;
    dim3 grid(slices, BN * JN, CN / CG);
    float inv_w = 1.0f / (float)max_w;
    roirotate_kernel<<<grid, block>>>(image, boxes, out, max_w, inv_w);
}

// round 11
// speedup vs baseline: 1.4932x; 1.1096x over previous
#include <cuda_runtime.h>
#include <stdint.h>

#define BN 8
#define JN 64
#define CN 32
#define CG 16              // channels per interp-block group (2 groups)
#define HT 8
#define HIMG_ 256
#define WIMG_ 256
#define HW (HIMG_*WIMG_)

#define NZBLK (BN*JN*4)    // 2048 zerofill blocks: 4 per box, 64 rows each

__device__ __forceinline__ int box_width(const float* bx)
{
    float bw = bx[2] - bx[0];
    float bh = bx[3] - bx[1];
    // widths = int32( (bw/bh) * 8 ) in float32 arithmetic — keep EXACT
    return (int)(__fmul_rn(__fdiv_rn(bw, bh), 8.0f));
}

// One launch; blocks [0, NZBLK) stream zeros + mask, the rest interpolate.
__global__ void __launch_bounds__(256)
roirotate_fused(const float* __restrict__ image,
                const float* __restrict__ boxes,
                float* __restrict__ out,
                int max_w, float inv_w, int slices, int mask_mode)
{
    const int chw = HT * max_w;

    if (blockIdx.x < NZBLK) {
        // ============ zero-fill + mask ============
        const int z  = blockIdx.x;
        const int bj = z >> 2;
        const int rg = z & 3;                  // row group: rows [rg*64, rg*64+64)
        const int warp = threadIdx.x >> 5;
        const int lane = threadIdx.x & 31;

        const int width = box_width(boxes + bj * 5);

        // mask: one block per box writes it
        if (rg == 0) {
            if (mask_mode == 0) {
                float* maskp = out + BN * JN * CN * chw + bj * max_w;
                for (int k = threadIdx.x; k < max_w; k += blockDim.x)
                    maskp[k] = (k < width) ? 1.0f : 0.0f;
            } else if (mask_mode == 1) {
                unsigned char* maskp =
                    (unsigned char*)(out + BN * JN * CN * chw) + bj * max_w;
                for (int k = threadIdx.x; k < max_w; k += blockDim.x)
                    maskp[k] = (k < width) ? (unsigned char)1 : (unsigned char)0;
            }
        }

        const int kz = min(width, max_w);
        float* boxbase = out + bj * CN * chw;
        const float4 z4 = make_float4(0.f, 0.f, 0.f, 0.f);

        // 64 rows in this group, 8 warps -> 8 rows per warp
        #pragma unroll
        for (int j = 0; j < 8; j++) {
            int r = rg * 64 + warp * 8 + j;
            float* rowp = boxbase + r * max_w;

            // scalar head until (rowp + k) is 16B-aligned
            uintptr_t a4 = ((uintptr_t)(rowp + kz)) >> 2;
            int head = (int)((4 - (a4 & 3)) & 3);
            int k = kz;
            if (lane < head && k + lane < max_w)
                rowp[k + lane] = 0.0f;
            k += head;
            if (k > max_w) k = max_w;

            // float4 body, lanes stride 32 quads
            for (int kq = k + lane * 4; kq + 3 < max_w; kq += 128)
                *(float4*)(rowp + kq) = z4;

            // scalar tail
            int tail_start = k + ((max_w - k) & ~3);
            if (lane < (max_w - tail_start))
                rowp[tail_start + lane] = 0.0f;
        }
        return;
    }

    // ============ bilinear interpolation (live region) ============
    const int ib = blockIdx.x - NZBLK;
    const int bjcz = ib / slices;              // per-block scalar div: negligible
    const int slice = ib - bjcz * slices;
    const int bj = bjcz & (BN * JN - 1);       // BN*JN = 512
    const int cz = bjcz >> 9;
    const int b  = bj >> 6;                    // JN = 64
    const int c0 = cz * CG;

    const float* bx = boxes + bj * 5;
    float l = bx[0];
    float t = bx[1];

    const int width = box_width(bx);
    float bw = bx[2] - l;
    float bh = bx[3] - t;
    float each_w = bw / (float)(width - 1);
    float each_h = bh * (1.0f / 7.0f);         // HEIGHT-1 = 7

    const float* imgb = image + (b * CN + c0) * HW;
    float* outb = out + (bj * CN + c0) * chw;

    const int idx = slice * blockDim.x + threadIdx.x;   // over HT*max_w
    if (idx >= chw) return;

    // i = idx / max_w, k = idx % max_w via float reciprocal + exact fixup
    int i = (int)((float)idx * inv_w);
    int k = idx - i * max_w;
    if (k < 0)           { i--; k += max_w; }
    else if (k >= max_w) { i++; k -= max_w; }

    if (k >= width) return;                    // zerofill blocks own this region

    float x = (float)k * each_w + l;
    float y = (float)i * each_h + t;

    float fx = floorf(x), fy = floorf(y);
    int x0 = min(max((int)fx,     0), WIMG_ - 1);
    int x1 = min(max((int)fx + 1, 0), WIMG_ - 1);
    int y0 = min(max((int)fy,     0), HIMG_ - 1);
    int y1 = min(max((int)fy + 1, 0), HIMG_ - 1);

    float wx0 = x - (float)x0;
    float wx1 = (float)x1 - x;
    float wy0 = y - (float)y0;
    float wy1 = (float)y1 - y;

    float wa = wx1 * wy1;   // (y0,x0)
    float wb = wx1 * wy0;   // (y1,x0)
    float wc = wx0 * wy1;   // (y0,x1)
    float wd = wx0 * wy0;   // (y1,x1)

    const int o00 = y0 * WIMG_ + x0;
    const int o01 = y0 * WIMG_ + x1;
    const int o10 = y1 * WIMG_ + x0;
    const int o11 = y1 * WIMG_ + x1;

    const float* ip = imgb;
    float* o = outb + idx;
    #pragma unroll 8
    for (int c = 0; c < CG; c++) {
        float v = __ldg(ip + o00) * wa
                + __ldg(ip + o10) * wb
                + __ldg(ip + o01) * wc
                + __ldg(ip + o11) * wd;
        __stcg(o, v);
        ip += HW;
        o  += chw;
    }
}

extern "C" void kernel_launch(void* const* d_in, const int* in_sizes, int n_in,
                              void* d_out, int out_size)
{
    const float* image = (const float*)d_in[0];
    const float* boxes = (const float*)d_in[1];
    float* out = (float*)d_out;

    // Derive max_w from out_size (host-side, no sync needed).
    const long long per_res = (long long)BN * JN * CN * HT;     // 131072
    const long long per_fmask = per_res + (long long)BN * JN;   // 131584 (float mask)
    const long long per_u8 = per_res + (long long)BN * JN / 4;  // 131200 (u8 mask)

    int max_w, mask_mode;
    long long osz = (long long)out_size;
    if (osz % per_fmask == 0) {
        max_w = (int)(osz / per_fmask);
        mask_mode = 0;
    } else if (osz % per_u8 == 0) {
        max_w = (int)(osz / per_u8);
        mask_mode = 1;
    } else if (osz % per_res == 0) {
        max_w = (int)(osz / per_res);
        mask_mode = 2;
    } else {
        max_w = (int)(osz / per_fmask);
        mask_mode = 0;
    }

    const int block = 256;
    int slices = (HT * max_w + block - 1) / block;
    int ninterp = slices * BN * JN * (CN / CG);
    dim3 grid(NZBLK + ninterp);
    float inv_w = 1.0f / (float)max_w;
    roirotate_fused<<<grid, block>>>(image, boxes, out, max_w, inv_w, slices, mask_mode);
}

// round 12
// speedup vs baseline: 1.6998x; 1.1384x over previous
#include <cuda_runtime.h>

#define BN 8
#define JN 64
#define CN 32
#define CG 8               // channels per block group (grid.z = CN/CG = 4)
#define HT 8
#define HIMG_ 256
#define WIMG_ 256
#define HW (HIMG_*WIMG_)

// mask_mode: 0 = float mask after res, 1 = uint8 mask packed after res, 2 = no mask
__global__ void roirotate_kernel(const float* __restrict__ image,
                                 const float* __restrict__ boxes,
                                 float* __restrict__ out,
                                 int max_w, float inv_w, int mask_mode)
{
    const int bj = blockIdx.y;               // 0 .. B*J-1
    const int b  = bj >> 6;                  // JN = 64
    const int c0 = blockIdx.z * CG;

    const float* bx = boxes + bj * 5;
    float l   = bx[0];
    float t   = bx[1];
    float r   = bx[2];
    float btm = bx[3];

    float bw = r - l;
    float bh = btm - t;
    // widths = int32( (bw/bh) * 8 ) in float32 arithmetic — keep EXACT
    int width = (int)(__fmul_rn(__fdiv_rn(bw, bh), 8.0f));
    float each_w = bw / (float)(width - 1);
    float each_h = bh * (1.0f / 7.0f);        // HEIGHT-1 = 7

    const int chw = HT * max_w;               // per-channel output stride
    const float* imgb = image + (b * CN + c0) * HW;
    float* outb = out + (bj * CN + c0) * chw;

    // ---- mask (only one slice of blocks writes it) ----
    if (blockIdx.x == 0 && blockIdx.z == 0) {
        if (mask_mode == 0) {
            float* maskp = out + BN * JN * CN * chw + bj * max_w;
            for (int k = threadIdx.x; k < max_w; k += blockDim.x)
                maskp[k] = (k < width) ? 1.0f : 0.0f;
        } else if (mask_mode == 1) {
            unsigned char* maskp =
                (unsigned char*)(out + BN * JN * CN * chw) + bj * max_w;
            for (int k = threadIdx.x; k < max_w; k += blockDim.x)
                maskp[k] = (k < width) ? (unsigned char)1 : (unsigned char)0;
        }
    }

    const int idx = blockIdx.x * blockDim.x + threadIdx.x;   // over HT*max_w
    if (idx >= chw) return;

    // i = idx / max_w, k = idx % max_w via float reciprocal + exact fixup
    int i = (int)((float)idx * inv_w);
    int k = idx - i * max_w;
    if (k < 0)           { i--; k += max_w; }
    else if (k >= max_w) { i++; k -= max_w; }

    float* op = outb + idx;                   // == outb + i*max_w + k

    if (k >= width) {
        // masked region -> zeros (buffer poisoned, must write); coalesced per warp
        float* o = op;
        #pragma unroll
        for (int c = 0; c < CG; c++) { *o = 0.0f; o += chw; }
        return;
    }

    float x = (float)k * each_w + l;
    float y = (float)i * each_h + t;

    float fx = floorf(x), fy = floorf(y);
    int x0 = min(max((int)fx,     0), WIMG_ - 1);
    int x1 = min(max((int)fx + 1, 0), WIMG_ - 1);
    int y0 = min(max((int)fy,     0), HIMG_ - 1);
    int y1 = min(max((int)fy + 1, 0), HIMG_ - 1);

    float wx0 = x - (float)x0;     // weight for x1 side
    float wx1 = (float)x1 - x;     // weight for x0 side
    float wy0 = y - (float)y0;
    float wy1 = (float)y1 - y;

    float wa = wx1 * wy1;   // (y0,x0)
    float wb = wx1 * wy0;   // (y1,x0)
    float wc = wx0 * wy1;   // (y0,x1)
    float wd = wx0 * wy0;   // (y1,x1)

    const int o00 = y0 * WIMG_ + x0;
    const int o01 = y0 * WIMG_ + x1;
    const int o10 = y1 * WIMG_ + x0;
    const int o11 = y1 * WIMG_ + x1;

    const float* ip = imgb;
    float* o = op;
    #pragma unroll
    for (int c = 0; c < CG; c++) {
        float v = __ldg(ip + o00) * wa
                + __ldg(ip + o10) * wb
                + __ldg(ip + o01) * wc
                + __ldg(ip + o11) * wd;
        *o = v;
        ip += HW;
        o  += chw;
    }
}

extern "C" void kernel_launch(void* const* d_in, const int* in_sizes, int n_in,
                              void* d_out, int out_size)
{
    const float* image = (const float*)d_in[0];
    const float* boxes = (const float*)d_in[1];
    float* out = (float*)d_out;

    // Derive max_w from out_size (host-side, no sync needed).
    const long long per_res = (long long)BN * JN * CN * HT;     // 131072
    const long long per_fmask = per_res + (long long)BN * JN;   // 131584 (float mask)
    const long long per_u8 = per_res + (long long)BN * JN / 4;  // 131200 (u8 mask)

    int max_w, mask_mode;
    long long osz = (long long)out_size;
    if (osz % per_fmask == 0) {
        max_w = (int)(osz / per_fmask);
        mask_mode = 0;
    } else if (osz % per_u8 == 0) {
        max_w = (int)(osz / per_u8);
        mask_mode = 1;
    } else if (osz % per_res == 0) {
        max_w = (int)(osz / per_res);
        mask_mode = 2;
    } else {
        max_w = (int)(osz / per_fmask);
        mask_mode = 0;
    }

    const int block = 256;
    int slices = (HT * max_w + block - 1) / block;
    dim3 grid(slices, BN * JN, CN / CG);
    float inv_w = 1.0f / (float)max_w;
    roirotate_kernel<<<grid, block>>>(image, boxes, out, max_w, inv_w, mask_mode);
}